// round 16
// baseline (speedup 1.0000x reference)
#include <cuda_runtime.h>
#include <math.h>

#define BB   8
#define NN   8192
#define MM   2048
#define KK   32
#define CIN  64
#define KD0  67
#define RTOT (BB*MM*KK)

__device__ float g_featT[(size_t)BB * NN * CIN];
__device__ float g_Y0[(size_t)RTOT * 64];
__device__ float g_Y1[(size_t)RTOT * 64];
__device__ float g_Ymax[(size_t)BB * MM * 128];
__device__ int   g_knn[(size_t)BB * MM * KK];
__device__ float g_stats0[128];
__device__ float g_stats1[128];
__device__ float g_stats2[256];

__device__ __forceinline__ float sq3_rn(float x, float y, float z) {
    return __fadd_rn(__fadd_rn(__fmul_rn(x, x), __fmul_rn(y, y)), __fmul_rn(z, z));
}
__device__ __forceinline__ void bn_ss(const float* stats, int sqoff,
                                      const float* gprm, const float* btprm,
                                      int c, float& sc, float& sh) {
    const float inv = 1.0f / (float)RTOT;
    float mu  = stats[c] * inv;
    float ex2 = stats[sqoff + c] * inv;
    float var = ex2 - mu * mu;
    float s   = gprm[c] * rsqrtf(var + 1e-5f);
    sc = s;
    sh = btprm[c] - mu * s;
}
__device__ __forceinline__ unsigned long long pk2(float lo, float hi) {
    unsigned long long r;
    asm("mov.b64 %0, {%1, %2};" : "=l"(r) : "f"(lo), "f"(hi));
    return r;
}
__device__ __forceinline__ void unpk2(unsigned long long v, float& lo, float& hi) {
    asm("mov.b64 {%0, %1}, %2;" : "=f"(lo), "=f"(hi) : "l"(v));
}
__device__ __forceinline__ unsigned long long fma2_(unsigned long long a, unsigned long long b, unsigned long long c) {
    unsigned long long d;
    asm("fma.rn.f32x2 %0, %1, %2, %3;" : "=l"(d) : "l"(a), "l"(b), "l"(c));
    return d;
}
__device__ __forceinline__ unsigned long long mul2_(unsigned long long a, unsigned long long b) {
    unsigned long long d;
    asm("mul.rn.f32x2 %0, %1, %2;" : "=l"(d) : "l"(a), "l"(b));
    return d;
}
__device__ __forceinline__ unsigned long long add2_(unsigned long long a, unsigned long long b) {
    unsigned long long d;
    asm("add.rn.f32x2 %0, %1, %2;" : "=l"(d) : "l"(a), "l"(b));
    return d;
}

// ---- cluster helpers ----
__device__ __forceinline__ unsigned smem_u32(const void* p) {
    unsigned a;
    asm("{ .reg .u64 t; cvta.to.shared.u64 t, %1; cvt.u32.u64 %0, t; }" : "=r"(a) : "l"(p));
    return a;
}
__device__ __forceinline__ unsigned ctarank() {
    unsigned r; asm("mov.u32 %0, %%cluster_ctarank;" : "=r"(r)); return r;
}
__device__ __forceinline__ void dsm_put_key(unsigned addr, int rank, unsigned long long v) {
    unsigned rem;
    asm("mapa.shared::cluster.u32 %0, %1, %2;" : "=r"(rem) : "r"(addr), "r"(rank));
    asm volatile("st.shared::cluster.u64 [%0], %1;" :: "r"(rem), "l"(v) : "memory");
}
__device__ __forceinline__ void dsm_arrive(unsigned mbar, int rank) {
    unsigned rem;
    asm("mapa.shared::cluster.u32 %0, %1, %2;" : "=r"(rem) : "r"(mbar), "r"(rank));
    asm volatile("mbarrier.arrive.release.cluster.shared::cluster.b64 _, [%0];" :: "r"(rem) : "memory");
}
__device__ __forceinline__ void mbar_wait_cl(unsigned mbar, unsigned parity) {
    asm volatile(
        "{\n\t.reg .pred P1;\n\t"
        "WL_%=:\n\t"
        "mbarrier.try_wait.parity.acquire.cluster.shared::cta.b64 P1, [%0], %1, 0x989680;\n\t"
        "@P1 bra.uni WD_%=;\n\t"
        "bra.uni WL_%=;\n\t"
        "WD_%=:\n\t}"
        :: "r"(mbar), "r"(parity) : "memory");
}

// ---------------- fused: cluster-FPS (blocks 0-31) + transpose (32+) --------
#define FPS_T 512
__global__ void __launch_bounds__(FPS_T) __cluster_dims__(4, 1, 1)
k_fps_tr(const float* __restrict__ xyz,
         const float* __restrict__ feat,
         float* __restrict__ out_xyz) {
    __shared__ union {
        struct { unsigned d[2][16], i[2][16]; } red;
        float tile[2][32][33];
    } smu;
    __shared__ unsigned long long s_key[2][4];
    __shared__ unsigned long long s_mbar;

    int bid = blockIdx.x;
    int t = threadIdx.x;

    if (bid >= 32) {
        if (bid == 32) {
            if (t < 128)      g_stats0[t] = 0.0f;
            else if (t < 256) g_stats1[t - 128] = 0.0f;
            else              g_stats2[t - 256] = 0.0f;
        }
        int half = t >> 8;
        int tx = t & 31, ty = (t >> 5) & 7;
        int t2 = (bid - 32) * 2 + half;
        int n0 = (t2 & 255) * 32;
        int c0 = ((t2 >> 8) & 1) * 32;
        int b  = t2 >> 9;
        #pragma unroll
        for (int i = 0; i < 32; i += 8)
            smu.tile[half][ty + i][tx] =
                feat[((size_t)b * CIN + (c0 + ty + i)) * NN + n0 + tx];
        __syncthreads();
        #pragma unroll
        for (int i = 0; i < 32; i += 8)
            g_featT[((size_t)b * NN + (n0 + ty + i)) * CIN + c0 + tx] =
                smu.tile[half][tx][ty + i];
        return;
    }

    // ---- FPS: 4 CTAs per batch; this CTA owns points [rank*2048, +2048) ----
    int b    = bid >> 2;
    int rank = (int)ctarank();
    int w = t >> 5, lane = t & 31;
    const float* xb = xyz + (size_t)b * NN * 3;
    int pbase = rank * 2048;

    unsigned mbar_a = smem_u32(&s_mbar);
    unsigned key_a  = smem_u32(&s_key[0][0]);

    if (t == 0) {
        asm volatile("mbarrier.init.shared.b64 [%0], 4;" :: "r"(mbar_a) : "memory");
    }
    __syncthreads();
    asm volatile("barrier.cluster.arrive.aligned;" ::: "memory");
    asm volatile("barrier.cluster.wait.aligned;" ::: "memory");

    // 4 points per thread = 2 packed pairs: p_i = pbase + i*512 + t
    unsigned long long pxp[2], pyp[2], pzp[2];
    float dist[4];
    #pragma unroll
    for (int jp = 0; jp < 2; jp++) {
        int p0 = pbase + (2 * jp) * 512 + t;
        int p1 = pbase + (2 * jp + 1) * 512 + t;
        pxp[jp] = pk2(xb[p0 * 3 + 0], xb[p1 * 3 + 0]);
        pyp[jp] = pk2(xb[p0 * 3 + 1], xb[p1 * 3 + 1]);
        pzp[jp] = pk2(xb[p0 * 3 + 2], xb[p1 * 3 + 2]);
    }
    #pragma unroll
    for (int i = 0; i < 4; i++) dist[i] = 1e10f;

    const unsigned long long one2 = pk2(1.0f, 1.0f);
    float cx = xb[0], cy = xb[1], cz = xb[2];

    for (int m = 0; m < MM; m++) {
        if (rank == 0 && t == 0) {
            float* o = out_xyz + ((size_t)b * MM + m) * 3;
            o[0] = cx; o[1] = cy; o[2] = cz;
        }
        unsigned long long ncx = pk2(-cx, -cx);
        unsigned long long ncy = pk2(-cy, -cy);
        unsigned long long ncz = pk2(-cz, -cz);
        #pragma unroll
        for (int jp = 0; jp < 2; jp++) {
            unsigned long long dx = fma2_(pxp[jp], one2, ncx);
            unsigned long long dy = fma2_(pyp[jp], one2, ncy);
            unsigned long long dz = fma2_(pzp[jp], one2, ncz);
            unsigned long long s  = add2_(add2_(mul2_(dx, dx), mul2_(dy, dy)), mul2_(dz, dz));
            float s0, s1;
            unpk2(s, s0, s1);
            dist[2 * jp]     = fminf(dist[2 * jp], s0);
            dist[2 * jp + 1] = fminf(dist[2 * jp + 1], s1);
        }
        // per-thread argmax over 4 (tie -> smaller i)
        float bd = dist[0]; int bi = 0;
        if (dist[1] > bd) { bd = dist[1]; bi = 1; }
        if (dist[2] > bd) { bd = dist[2]; bi = 2; }
        if (dist[3] > bd) { bd = dist[3]; bi = 3; }

        unsigned hb   = __float_as_uint(bd);
        unsigned binv = (unsigned)(0x00FFFFFF - (pbase + bi * 512 + t));
        unsigned wd = __reduce_max_sync(0xffffffffu, hb);
        unsigned wi = __reduce_max_sync(0xffffffffu, (hb == wd) ? binv : 0u);
        int buf = m & 1;
        if (lane == 0) { smu.red.d[buf][w] = wd; smu.red.i[buf][w] = wi; }
        __syncthreads();
        unsigned vd = (lane < 16) ? smu.red.d[buf][lane] : 0u;
        unsigned vi = (lane < 16) ? smu.red.i[buf][lane] : 0u;
        unsigned gd = __reduce_max_sync(0xffffffffu, vd);
        unsigned gi = __reduce_max_sync(0xffffffffu, (vd == gd) ? vi : 0u);

        // exchange CTA winners across the cluster
        if (t == 0) {
            unsigned long long key = ((unsigned long long)gd << 32) | gi;
            unsigned slot = key_a + (unsigned)(buf * 4 + rank) * 8;
            #pragma unroll
            for (int r = 0; r < 4; r++) dsm_put_key(slot, r, key);
            #pragma unroll
            for (int r = 0; r < 4; r++) dsm_arrive(mbar_a, r);
        }
        mbar_wait_cl(mbar_a, (unsigned)buf);

        unsigned long long k0 = s_key[buf][0];
        unsigned long long k1 = s_key[buf][1];
        unsigned long long k2 = s_key[buf][2];
        unsigned long long k3 = s_key[buf][3];
        unsigned long long ka = (k0 > k1) ? k0 : k1;
        unsigned long long kb = (k2 > k3) ? k2 : k3;
        unsigned long long km = (ka > kb) ? ka : kb;
        int idx = 0x00FFFFFF - (int)(unsigned)(km & 0xFFFFFFFFULL);
        cx = xb[idx * 3 + 0];
        cy = xb[idx * 3 + 1];
        cz = xb[idx * 3 + 2];
    }
}

// ---------------- ball query (unchanged) ----------------
#define BQ_T    128
#define BQ_TILE 1024
__global__ void __launch_bounds__(BQ_T) k_ballquery(const float* __restrict__ xyz,
                                                    const float* __restrict__ newxyz) {
    __shared__ float4 sp[BQ_TILE];
    int b = blockIdx.x >> 4;
    int m = (blockIdx.x & 15) * BQ_T + threadIdx.x;
    const float* xb = xyz + (size_t)b * NN * 3;

    float cx = newxyz[((size_t)b * MM + m) * 3 + 0];
    float cy = newxyz[((size_t)b * MM + m) * 3 + 1];
    float cz = newxyz[((size_t)b * MM + m) * 3 + 2];
    float c2 = sq3_rn(cx, cy, cz);

    double mid = 0.5 * ((double)0.4f + (double)nextafterf(0.4f, 1.0f));
    double Td  = mid * mid;
    float  Tf  = (float)Td;
    if ((double)Tf >= Td) Tf = nextafterf(Tf, 0.0f);

    unsigned long long list[KK];
    #pragma unroll
    for (int k = 0; k < KK; k++) list[k] = 0xFFFFFFFFFFFFFFFFULL;
    unsigned long long worst = 0xFFFFFFFFFFFFFFFFULL;

    for (int tb = 0; tb < NN; tb += BQ_TILE) {
        __syncthreads();
        for (int f = threadIdx.x; f < BQ_TILE; f += BQ_T) {
            float x = xb[(tb + f) * 3 + 0];
            float y = xb[(tb + f) * 3 + 1];
            float z = xb[(tb + f) * 3 + 2];
            sp[f] = make_float4(x, y, z, sq3_rn(x, y, z));
        }
        __syncthreads();

        for (int j = 0; j < BQ_TILE; j++) {
            float4 p = sp[j];
            float dot = __fadd_rn(__fadd_rn(__fmul_rn(cx, p.x), __fmul_rn(cy, p.y)), __fmul_rn(cz, p.z));
            float d2  = __fsub_rn(__fadd_rn(c2, p.w), __fmul_rn(2.0f, dot));
            d2 = fmaxf(d2, 0.0f);
            unsigned bits = (d2 <= Tf) ? __float_as_uint(d2) : 0x7f800000u;
            unsigned long long key = ((unsigned long long)bits << 32) | (unsigned)(tb + j);
            if (key < worst) {
                unsigned long long cur = key;
                #pragma unroll
                for (int k = 0; k < KK; k++) {
                    unsigned long long lo = (cur < list[k]) ? cur : list[k];
                    unsigned long long hi = (cur < list[k]) ? list[k] : cur;
                    list[k] = lo;
                    cur = hi;
                }
                worst = list[KK - 1];
            }
        }
    }

    int* o = g_knn + (size_t)(b * MM + m) * KK;
    #pragma unroll
    for (int k = 0; k < KK; k++) o[k] = (int)(list[k] & 0xffffffffULL);
}

// ---------------- GEMM core (unchanged R9 pair-A) ----------------
#define XS_LD  130
#define XS_BYTES  (68 * XS_LD * 4)
#define WSD_BYTES (68 * 64 * 8)
#define GEMM_SMEM (XS_BYTES + WSD_BYTES)

struct ABuf { unsigned long long a[4]; unsigned long long b[8]; };

__device__ __forceinline__ void ld_ab(const float* xp, const unsigned long long* wp,
                                      int k, ABuf& r) {
    #pragma unroll
    for (int q = 0; q < 4; q++)
        r.a[q] = *(const unsigned long long*)(xp + k * XS_LD + 32 * q);
    ulonglong2 b01 = *(const ulonglong2*)(wp + (size_t)k * 64 + 0);
    ulonglong2 b23 = *(const ulonglong2*)(wp + (size_t)k * 64 + 2);
    ulonglong2 b45 = *(const ulonglong2*)(wp + (size_t)k * 64 + 4);
    ulonglong2 b67 = *(const ulonglong2*)(wp + (size_t)k * 64 + 6);
    r.b[0] = b01.x; r.b[1] = b01.y; r.b[2] = b23.x; r.b[3] = b23.y;
    r.b[4] = b45.x; r.b[5] = b45.y; r.b[6] = b67.x; r.b[7] = b67.y;
}
__device__ __forceinline__ void fma_ab(unsigned long long acc[4][8], const ABuf& r) {
    #pragma unroll
    for (int q = 0; q < 4; q++)
        #pragma unroll
        for (int j = 0; j < 8; j++)
            asm("fma.rn.f32x2 %0, %1, %2, %0;" : "+l"(acc[q][j]) : "l"(r.a[q]), "l"(r.b[j]));
}
template <int KD>
__device__ __forceinline__ void gemm_mainloop(const float* Xs, const unsigned long long* Wsd,
                                              int t, unsigned long long acc[4][8]) {
    int rg = t & 15, cg = t >> 4;
    #pragma unroll
    for (int q = 0; q < 4; q++)
        #pragma unroll
        for (int j = 0; j < 8; j++) acc[q][j] = 0ULL;
    const unsigned long long* wp = Wsd + cg * 8;
    const float* xp = Xs + 2 * rg;
    ABuf A, B;
    constexpr int MAIN = (KD - 2) & ~1;
    ld_ab(xp, wp, 0, A);
    #pragma unroll 4
    for (int k = 0; k < MAIN; k += 2) {
        ld_ab(xp, wp, k + 1, B);
        fma_ab(acc, A);
        ld_ab(xp, wp, k + 2, A);
        fma_ab(acc, B);
    }
    ld_ab(xp, wp, MAIN + 1, B);
    fma_ab(acc, A);
    if (KD - MAIN == 3) {
        ld_ab(xp, wp, MAIN + 2, A);
        fma_ab(acc, B);
        fma_ab(acc, A);
    } else {
        fma_ab(acc, B);
    }
}

__device__ __forceinline__ void gemm_epi_store(
    unsigned long long acc[4][8], float* Xs,
    const float* bias, float* Y, int ldy,
    size_t row0, int col0, int t,
    float* stats, int sqoff)
{
    int rg = t & 15, cg = t >> 4;
    float bsum[8], bsq[8], bval[8];
    #pragma unroll
    for (int j = 0; j < 8; j++) { bsum[j] = 0.f; bsq[j] = 0.f; bval[j] = bias[col0 + cg * 8 + j]; }
    #pragma unroll
    for (int q = 0; q < 4; q++) {
        size_t r0 = row0 + 2 * rg + 32 * q;
        float y0[8], y1[8];
        #pragma unroll
        for (int j = 0; j < 8; j++) {
            float lo, hi;
            unpk2(acc[q][j], lo, hi);
            y0[j] = lo + bval[j];
            y1[j] = hi + bval[j];
            bsum[j] += y0[j] + y1[j];
            bsq[j]  = fmaf(y0[j], y0[j], fmaf(y1[j], y1[j], bsq[j]));
        }
        float* ya = Y + r0 * (size_t)ldy + col0 + cg * 8;
        float* yb = ya + ldy;
        *(float4*)(ya)     = make_float4(y0[0], y0[1], y0[2], y0[3]);
        *(float4*)(ya + 4) = make_float4(y0[4], y0[5], y0[6], y0[7]);
        *(float4*)(yb)     = make_float4(y1[0], y1[1], y1[2], y1[3]);
        *(float4*)(yb + 4) = make_float4(y1[4], y1[5], y1[6], y1[7]);
    }
    __syncthreads();
    float* csum = Xs;
    float* csq  = Xs + 64;
    if (t < 64) { csum[t] = 0.f; csq[t] = 0.f; }
    __syncthreads();
    #pragma unroll
    for (int j = 0; j < 8; j++) {
        atomicAdd(&csum[cg * 8 + j], bsum[j]);
        atomicAdd(&csq[cg * 8 + j], bsq[j]);
    }
    __syncthreads();
    if (t < 64) {
        atomicAdd(&stats[col0 + t], csum[t]);
        atomicAdd(&stats[sqoff + col0 + t], csq[t]);
    }
}

__device__ __forceinline__ void gemm_epi_max(
    unsigned long long acc[4][8], float* scr,
    const float* bias, size_t row0, int col0, int t,
    float* stats, int sqoff)
{
    int rg = t & 15, cg = t >> 4;
    int bm0 = (int)(row0 >> 5);
    float* sMax = scr;
    float* csum = scr + 4352;
    float* csq  = scr + 4416;

    float bsum[8], bsq[8], bval[8];
    #pragma unroll
    for (int j = 0; j < 8; j++) { bsum[j] = 0.f; bsq[j] = 0.f; bval[j] = bias[col0 + cg * 8 + j]; }
    #pragma unroll
    for (int q = 0; q < 4; q++) {
        #pragma unroll
        for (int j = 0; j < 8; j++) {
            float lo, hi;
            unpk2(acc[q][j], lo, hi);
            float y0 = lo + bval[j];
            float y1 = hi + bval[j];
            bsum[j] += y0 + y1;
            bsq[j]  = fmaf(y0, y0, fmaf(y1, y1, bsq[j]));
            sMax[(q * 64 + cg * 8 + j) * 17 + rg] = fmaxf(y0, y1);
        }
    }
    if (t < 64) { csum[t] = 0.f; csq[t] = 0.f; }
    __syncthreads();
    #pragma unroll
    for (int j = 0; j < 8; j++) {
        atomicAdd(&csum[cg * 8 + j], bsum[j]);
        atomicAdd(&csq[cg * 8 + j], bsq[j]);
    }
    __syncthreads();
    if (t < 64) {
        atomicAdd(&stats[col0 + t], csum[t]);
        atomicAdd(&stats[sqoff + col0 + t], csq[t]);
    }
    #pragma unroll
    for (int e = t; e < 256; e += 128) {
        int q = e >> 6, col = e & 63;
        const float* p = &sMax[(q * 64 + col) * 17];
        float mx = p[0];
        #pragma unroll
        for (int r = 1; r < 16; r++) mx = fmaxf(mx, p[r]);
        g_Ymax[(size_t)(bm0 + q) * 128 + col0 + col] = mx;
    }
}

__global__ void __launch_bounds__(128, 3) k_gemm0(const float* __restrict__ xyz,
                                                  const float* __restrict__ newxyz,
                                                  const float* __restrict__ W,
                                                  const float* __restrict__ bias,
                                                  float* __restrict__ Y) {
    extern __shared__ float sm[];
    float* Xs = sm;
    unsigned long long* Wsd = (unsigned long long*)(sm + 68 * XS_LD);
    int t = threadIdx.x, w = t >> 5, lane = t & 31;
    size_t row0 = (size_t)blockIdx.x * 128;
    int bm0 = (int)(row0 >> 5);
    int b   = bm0 >> 11;

    __shared__ int   s_idx[128];
    __shared__ float s_ctr[4][3];
    s_idx[t] = g_knn[row0 + t];
    if (t < 12) s_ctr[t / 3][t % 3] = newxyz[(size_t)bm0 * 3 + t];
    __syncthreads();

    const float* fb = g_featT + (size_t)b * NN * CIN;
    const float* xb = xyz + (size_t)b * NN * 3;

    float ctr = (lane < 3) ? s_ctr[w][lane] : 0.0f;
    #pragma unroll 4
    for (int rr = 0; rr < 32; rr++) {
        int r = w * 32 + rr;
        int n = s_idx[r];
        float2 v = *(const float2*)(fb + (size_t)n * CIN + lane * 2);
        Xs[(2 * lane) * XS_LD + r]     = v.x;
        Xs[(2 * lane + 1) * XS_LD + r] = v.y;
        if (lane < 3)
            Xs[(64 + lane) * XS_LD + r] = __fsub_rn(xb[n * 3 + lane], ctr);
    }
    {
        int tot = 64 * KD0;
        for (int e = t; e < tot; e += 128) {
            int o = e / KD0, k = e - o * KD0;
            int kk = (k < 64) ? (k + 3) : (k - 64);
            float wv = W[o * KD0 + kk];
            Wsd[k * 64 + o] = pk2(wv, wv);
        }
    }
    __syncthreads();
    unsigned long long acc[4][8];
    gemm_mainloop<KD0>(Xs, Wsd, t, acc);
    gemm_epi_store(acc, Xs, bias, Y, 64, row0, 0, t, g_stats0, 64);
}

__global__ void __launch_bounds__(128, 3) k_gemmx(const float* __restrict__ X,
                                                  const float* __restrict__ W,
                                                  const float* __restrict__ bias,
                                                  const float* __restrict__ gprm,
                                                  const float* __restrict__ btprm,
                                                  float* __restrict__ Y, int ldy) {
    extern __shared__ float sm[];
    float* Xs = sm;
    unsigned long long* Wsd = (unsigned long long*)(sm + 68 * XS_LD);
    int t = threadIdx.x;
    size_t row0 = (size_t)blockIdx.x * 128;
    int col0 = 0;
    {
        const float* xr = X + row0 * 64;
        int c = (t * 4) & 63;
        float sc[4], sh[4];
        #pragma unroll
        for (int q = 0; q < 4; q++) bn_ss(g_stats0, 64, gprm, btprm, c + q, sc[q], sh[q]);
        #pragma unroll
        for (int it = 0; it < 16; it++) {
            int idx = it * 512 + t * 4;
            int r = idx >> 6;
            float4 v = *(const float4*)(xr + idx);
            v.x = fmaxf(fmaf(v.x, sc[0], sh[0]), 0.0f);
            v.y = fmaxf(fmaf(v.y, sc[1], sh[1]), 0.0f);
            v.z = fmaxf(fmaf(v.z, sc[2], sh[2]), 0.0f);
            v.w = fmaxf(fmaf(v.w, sc[3], sh[3]), 0.0f);
            Xs[(c + 0) * XS_LD + r] = v.x;
            Xs[(c + 1) * XS_LD + r] = v.y;
            Xs[(c + 2) * XS_LD + r] = v.z;
            Xs[(c + 3) * XS_LD + r] = v.w;
        }
    }
    {
        const float* wb = W;
        #pragma unroll 4
        for (int e = t; e < 64 * 64; e += 128) {
            int o = e >> 6, k = e & 63;
            float wv = wb[o * 64 + k];
            Wsd[k * 64 + o] = pk2(wv, wv);
        }
    }
    __syncthreads();
    unsigned long long acc[4][8];
    gemm_mainloop<64>(Xs, Wsd, t, acc);
    gemm_epi_store(acc, Xs, bias, Y, ldy, row0, col0, t, g_stats1, 64);
}

__global__ void __launch_bounds__(128, 3) k_gemmf(const float* __restrict__ X,
                                                  const float* __restrict__ W,
                                                  const float* __restrict__ bias,
                                                  const float* __restrict__ gprm,
                                                  const float* __restrict__ btprm) {
    extern __shared__ float sm[];
    float* Xs = sm;
    unsigned long long* Wsd = (unsigned long long*)(sm + 68 * XS_LD);
    int t = threadIdx.x;
    size_t row0 = (size_t)blockIdx.x * 128;
    {
        const float* xr = X + row0 * 64;
        int c = (t * 4) & 63;
        float sc[4], sh[4];
        #pragma unroll
        for (int q = 0; q < 4; q++) bn_ss(g_stats1, 64, gprm, btprm, c + q, sc[q], sh[q]);
        #pragma unroll
        for (int it = 0; it < 16; it++) {
            int idx = it * 512 + t * 4;
            int r = idx >> 6;
            float4 v = *(const float4*)(xr + idx);
            v.x = fmaxf(fmaf(v.x, sc[0], sh[0]), 0.0f);
            v.y = fmaxf(fmaf(v.y, sc[1], sh[1]), 0.0f);
            v.z = fmaxf(fmaf(v.z, sc[2], sh[2]), 0.0f);
            v.w = fmaxf(fmaf(v.w, sc[3], sh[3]), 0.0f);
            Xs[(c + 0) * XS_LD + r] = v.x;
            Xs[(c + 1) * XS_LD + r] = v.y;
            Xs[(c + 2) * XS_LD + r] = v.z;
            Xs[(c + 3) * XS_LD + r] = v.w;
        }
    }
    #pragma unroll
    for (int ct = 0; ct < 2; ct++) {
        int col0 = ct * 64;
        {
            const float* wb = W + (size_t)col0 * 64;
            #pragma unroll 4
            for (int e = t; e < 64 * 64; e += 128) {
                int o = e >> 6, k = e & 63;
                float wv = wb[o * 64 + k];
                Wsd[k * 64 + o] = pk2(wv, wv);
            }
        }
        __syncthreads();
        unsigned long long acc[4][8];
        gemm_mainloop<64>(Xs, Wsd, t, acc);
        __syncthreads();
        gemm_epi_max(acc, (float*)Wsd, bias, row0, col0, t, g_stats2, 128);
        __syncthreads();
    }
}

__global__ void __launch_bounds__(128) k_final2(const float* __restrict__ gprm,
                                                const float* __restrict__ btprm,
                                                float* __restrict__ out) {
    __shared__ float tile[32][129];
    int bm0 = blockIdx.x * 32;
    int c  = threadIdx.x;
    float sc, sh;
    bn_ss(g_stats2, 128, gprm, btprm, c, sc, sh);
    #pragma unroll 4
    for (int mm = 0; mm < 32; mm++) {
        float y = g_Ymax[(size_t)(bm0 + mm) * 128 + c];
        tile[mm][c] = fmaxf(fmaf(y, sc, sh), 0.0f);
    }
    __syncthreads();
    int b  = bm0 >> 11;
    int m0 = bm0 & 2047;
    int w = c >> 5, lane = c & 31;
    #pragma unroll 4
    for (int rr = 0; rr < 32; rr++) {
        int cc = w * 32 + rr;
        out[(size_t)BB * MM * 3 + ((size_t)b * 128 + cc) * MM + m0 + lane] = tile[lane][cc];
    }
}

extern "C" void kernel_launch(void* const* d_in, const int* in_sizes, int n_in,
                              void* d_out, int out_size) {
    const float* xyz  = (const float*)d_in[0];
    const float* feat = (const float*)d_in[1];
    const float* w0 = (const float*)d_in[2];
    const float* b0 = (const float*)d_in[3];
    const float* g0 = (const float*)d_in[4];
    const float* t0 = (const float*)d_in[5];
    const float* w1 = (const float*)d_in[6];
    const float* b1 = (const float*)d_in[7];
    const float* g1 = (const float*)d_in[8];
    const float* t1 = (const float*)d_in[9];
    const float* w2 = (const float*)d_in[10];
    const float* b2 = (const float*)d_in[11];
    const float* g2 = (const float*)d_in[12];
    const float* t2 = (const float*)d_in[13];
    float* out = (float*)d_out;

    void *pY0, *pY1;
    cudaGetSymbolAddress(&pY0, g_Y0);
    cudaGetSymbolAddress(&pY1, g_Y1);
    float* Y0 = (float*)pY0;
    float* Y1 = (float*)pY1;

    cudaFuncSetAttribute(k_gemm0, cudaFuncAttributeMaxDynamicSharedMemorySize, GEMM_SMEM);
    cudaFuncSetAttribute(k_gemmx, cudaFuncAttributeMaxDynamicSharedMemorySize, GEMM_SMEM);
    cudaFuncSetAttribute(k_gemmf, cudaFuncAttributeMaxDynamicSharedMemorySize, GEMM_SMEM);

    // 32 FPS blocks (8 clusters of 4) + 2048 transpose blocks; 2080 % 4 == 0
    k_fps_tr<<<32 + 2048, FPS_T>>>(xyz, feat, out);
    k_ballquery<<<BB * (MM / BQ_T), BQ_T>>>(xyz, out);
    k_gemm0<<<RTOT / 128, 128, GEMM_SMEM>>>(xyz, out, w0, b0, Y0);
    k_gemmx<<<RTOT / 128, 128, GEMM_SMEM>>>(Y0, w1, b1, g0, t0, Y1, 64);
    k_gemmf<<<RTOT / 128, 128, GEMM_SMEM>>>(Y1, w2, b2, g1, t1);
    k_final2<<<BB * MM / 32, 128>>>(g2, t2, out);
}

// round 17
// speedup vs baseline: 2.4369x; 2.4369x over previous
#include <cuda_runtime.h>
#include <math.h>

#define BB   8
#define NN   8192
#define MM   2048
#define KK   32
#define CIN  64
#define KD0  67
#define RTOT (BB*MM*KK)

__device__ float g_featT[(size_t)BB * NN * CIN];
__device__ float g_Y0[(size_t)RTOT * 64];
__device__ float g_Y1[(size_t)RTOT * 64];
__device__ float g_Ymax[(size_t)BB * MM * 128];
__device__ int   g_knn[(size_t)BB * MM * KK];
__device__ float g_stats0[128];
__device__ float g_stats1[128];
__device__ float g_stats2[256];

__device__ __forceinline__ float sq3_rn(float x, float y, float z) {
    return __fadd_rn(__fadd_rn(__fmul_rn(x, x), __fmul_rn(y, y)), __fmul_rn(z, z));
}
__device__ __forceinline__ void bn_ss(const float* stats, int sqoff,
                                      const float* gprm, const float* btprm,
                                      int c, float& sc, float& sh) {
    const float inv = 1.0f / (float)RTOT;
    float mu  = stats[c] * inv;
    float ex2 = stats[sqoff + c] * inv;
    float var = ex2 - mu * mu;
    float s   = gprm[c] * rsqrtf(var + 1e-5f);
    sc = s;
    sh = btprm[c] - mu * s;
}
__device__ __forceinline__ unsigned long long pk2(float lo, float hi) {
    unsigned long long r;
    asm("mov.b64 %0, {%1, %2};" : "=l"(r) : "f"(lo), "f"(hi));
    return r;
}
__device__ __forceinline__ void unpk2(unsigned long long v, float& lo, float& hi) {
    asm("mov.b64 {%0, %1}, %2;" : "=f"(lo), "=f"(hi) : "l"(v));
}
__device__ __forceinline__ unsigned long long fma2_(unsigned long long a, unsigned long long b, unsigned long long c) {
    unsigned long long d;
    asm("fma.rn.f32x2 %0, %1, %2, %3;" : "=l"(d) : "l"(a), "l"(b), "l"(c));
    return d;
}
__device__ __forceinline__ unsigned long long mul2_(unsigned long long a, unsigned long long b) {
    unsigned long long d;
    asm("mul.rn.f32x2 %0, %1, %2;" : "=l"(d) : "l"(a), "l"(b));
    return d;
}
__device__ __forceinline__ unsigned long long add2_(unsigned long long a, unsigned long long b) {
    unsigned long long d;
    asm("add.rn.f32x2 %0, %1, %2;" : "=l"(d) : "l"(a), "l"(b));
    return d;
}

// ---- cluster helpers ----
__device__ __forceinline__ unsigned smem_u32(const void* p) {
    unsigned a;
    asm("{ .reg .u64 t; cvta.to.shared.u64 t, %1; cvt.u32.u64 %0, t; }" : "=r"(a) : "l"(p));
    return a;
}
__device__ __forceinline__ unsigned ctarank() {
    unsigned r; asm("mov.u32 %0, %%cluster_ctarank;" : "=r"(r)); return r;
}
__device__ __forceinline__ unsigned mapa_addr(unsigned addr, int rank) {
    unsigned rem;
    asm("mapa.shared::cluster.u32 %0, %1, %2;" : "=r"(rem) : "r"(addr), "r"(rank));
    return rem;
}
__device__ __forceinline__ void dsm_st_u64(unsigned raddr, unsigned long long v) {
    asm volatile("st.shared::cluster.u64 [%0], %1;" :: "r"(raddr), "l"(v) : "memory");
}

// ---------------- fused: cluster-FPS (blocks 0-31) + transpose (32+) --------
// FPS: 4 CTAs per batch; per step each CTA publishes its winner key to all 4
// CTAs with ONE fire-and-forget DSMEM store per peer (tag-in-key makes
// staleness detection exact; no mbarrier, no fences). Readers spin on local
// smem until all 4 tags match the step.
#define FPS_T 512
__global__ void __launch_bounds__(FPS_T) __cluster_dims__(4, 1, 1)
k_fps_tr(const float* __restrict__ xyz,
         const float* __restrict__ feat,
         float* __restrict__ out_xyz) {
    __shared__ union {
        struct { unsigned d[2][16], i[2][16]; } red;
        float tile[2][32][33];
    } smu;
    __shared__ unsigned long long s_key[4];   // one slot per rank (tagged)

    int bid = blockIdx.x;
    int t = threadIdx.x;

    if (bid >= 32) {
        if (bid == 32) {
            if (t < 128)      g_stats0[t] = 0.0f;
            else if (t < 256) g_stats1[t - 128] = 0.0f;
            else              g_stats2[t - 256] = 0.0f;
        }
        int half = t >> 8;
        int tx = t & 31, ty = (t >> 5) & 7;
        int t2 = (bid - 32) * 2 + half;
        int n0 = (t2 & 255) * 32;
        int c0 = ((t2 >> 8) & 1) * 32;
        int b  = t2 >> 9;
        #pragma unroll
        for (int i = 0; i < 32; i += 8)
            smu.tile[half][ty + i][tx] =
                feat[((size_t)b * CIN + (c0 + ty + i)) * NN + n0 + tx];
        __syncthreads();
        #pragma unroll
        for (int i = 0; i < 32; i += 8)
            g_featT[((size_t)b * NN + (n0 + ty + i)) * CIN + c0 + tx] =
                smu.tile[half][tx][ty + i];
        return;
    }

    // ---- FPS: CTA owns points [rank*2048, +2048), 4 per thread ----
    int b    = bid >> 2;
    int rank = (int)ctarank();
    int w = t >> 5, lane = t & 31;
    const float* xb = xyz + (size_t)b * NN * 3;
    int pbase = rank * 2048;

    // init own slots to invalid tag 0xFFF (m <= 2047 never matches)
    if (t < 4) s_key[t] = 0xFFFULL;
    __syncthreads();
    asm volatile("barrier.cluster.arrive.aligned;" ::: "memory");
    asm volatile("barrier.cluster.wait.aligned;" ::: "memory");

    // precompute remote addresses of MY slot in every CTA
    unsigned raddr[4];
    {
        unsigned myslot = smem_u32(&s_key[rank]);
        #pragma unroll
        for (int r = 0; r < 4; r++) raddr[r] = mapa_addr(myslot, r);
    }
    volatile unsigned long long* vk = s_key;

    unsigned long long pxp[2], pyp[2], pzp[2];
    float dist[4];
    #pragma unroll
    for (int jp = 0; jp < 2; jp++) {
        int p0 = pbase + (2 * jp) * 512 + t;
        int p1 = pbase + (2 * jp + 1) * 512 + t;
        pxp[jp] = pk2(xb[p0 * 3 + 0], xb[p1 * 3 + 0]);
        pyp[jp] = pk2(xb[p0 * 3 + 1], xb[p1 * 3 + 1]);
        pzp[jp] = pk2(xb[p0 * 3 + 2], xb[p1 * 3 + 2]);
    }
    #pragma unroll
    for (int i = 0; i < 4; i++) dist[i] = 1e10f;

    const unsigned long long one2 = pk2(1.0f, 1.0f);
    float cx = xb[0], cy = xb[1], cz = xb[2];

    for (int m = 0; m < MM; m++) {
        if (rank == 0 && t == 0) {
            float* o = out_xyz + ((size_t)b * MM + m) * 3;
            o[0] = cx; o[1] = cy; o[2] = cz;
        }
        unsigned long long ncx = pk2(-cx, -cx);
        unsigned long long ncy = pk2(-cy, -cy);
        unsigned long long ncz = pk2(-cz, -cz);
        #pragma unroll
        for (int jp = 0; jp < 2; jp++) {
            unsigned long long dx = fma2_(pxp[jp], one2, ncx);
            unsigned long long dy = fma2_(pyp[jp], one2, ncy);
            unsigned long long dz = fma2_(pzp[jp], one2, ncz);
            unsigned long long s  = add2_(add2_(mul2_(dx, dx), mul2_(dy, dy)), mul2_(dz, dz));
            float s0, s1;
            unpk2(s, s0, s1);
            dist[2 * jp]     = fminf(dist[2 * jp], s0);
            dist[2 * jp + 1] = fminf(dist[2 * jp + 1], s1);
        }
        float bd = dist[0]; int bi = 0;
        if (dist[1] > bd) { bd = dist[1]; bi = 1; }
        if (dist[2] > bd) { bd = dist[2]; bi = 2; }
        if (dist[3] > bd) { bd = dist[3]; bi = 3; }

        unsigned hb   = __float_as_uint(bd);
        unsigned binv = (unsigned)(0x1FFF - (pbase + bi * 512 + t));   // 13 bits
        unsigned wd = __reduce_max_sync(0xffffffffu, hb);
        unsigned wi = __reduce_max_sync(0xffffffffu, (hb == wd) ? binv : 0u);
        int buf = m & 1;
        if (lane == 0) { smu.red.d[buf][w] = wd; smu.red.i[buf][w] = wi; }
        __syncthreads();
        unsigned vd = (lane < 16) ? smu.red.d[buf][lane] : 0u;
        unsigned vi = (lane < 16) ? smu.red.i[buf][lane] : 0u;
        unsigned gd = __reduce_max_sync(0xffffffffu, vd);
        unsigned gi = __reduce_max_sync(0xffffffffu, (vd == gd) ? vi : 0u);

        // publish: one tagged store per peer (fire-and-forget)
        if (t == 0) {
            unsigned long long key =
                ((unsigned long long)gd << 32) | ((unsigned long long)gi << 12) | (unsigned)m;
            dsm_st_u64(raddr[0], key);
            dsm_st_u64(raddr[1], key);
            dsm_st_u64(raddr[2], key);
            dsm_st_u64(raddr[3], key);
        }
        // consume: spin until all 4 local slots carry this step's tag
        unsigned tagm = (unsigned)m;
        unsigned long long k0, k1, k2, k3;
        do {
            k0 = vk[0]; k1 = vk[1]; k2 = vk[2]; k3 = vk[3];
        } while ((((unsigned)k0 & 0xFFFu) != tagm) | (((unsigned)k1 & 0xFFFu) != tagm) |
                 (((unsigned)k2 & 0xFFFu) != tagm) | (((unsigned)k3 & 0xFFFu) != tagm));

        unsigned long long ka = (k0 > k1) ? k0 : k1;
        unsigned long long kb = (k2 > k3) ? k2 : k3;
        unsigned long long km = (ka > kb) ? ka : kb;
        int idx = 0x1FFF - (int)((km >> 12) & 0x1FFFULL);
        cx = xb[idx * 3 + 0];
        cy = xb[idx * 3 + 1];
        cz = xb[idx * 3 + 2];
    }
    asm volatile("barrier.cluster.arrive.aligned;" ::: "memory");
    asm volatile("barrier.cluster.wait.aligned;" ::: "memory");
}

// ---------------- ball query (unchanged) ----------------
#define BQ_T    128
#define BQ_TILE 1024
__global__ void __launch_bounds__(BQ_T) k_ballquery(const float* __restrict__ xyz,
                                                    const float* __restrict__ newxyz) {
    __shared__ float4 sp[BQ_TILE];
    int b = blockIdx.x >> 4;
    int m = (blockIdx.x & 15) * BQ_T + threadIdx.x;
    const float* xb = xyz + (size_t)b * NN * 3;

    float cx = newxyz[((size_t)b * MM + m) * 3 + 0];
    float cy = newxyz[((size_t)b * MM + m) * 3 + 1];
    float cz = newxyz[((size_t)b * MM + m) * 3 + 2];
    float c2 = sq3_rn(cx, cy, cz);

    double mid = 0.5 * ((double)0.4f + (double)nextafterf(0.4f, 1.0f));
    double Td  = mid * mid;
    float  Tf  = (float)Td;
    if ((double)Tf >= Td) Tf = nextafterf(Tf, 0.0f);

    unsigned long long list[KK];
    #pragma unroll
    for (int k = 0; k < KK; k++) list[k] = 0xFFFFFFFFFFFFFFFFULL;
    unsigned long long worst = 0xFFFFFFFFFFFFFFFFULL;

    for (int tb = 0; tb < NN; tb += BQ_TILE) {
        __syncthreads();
        for (int f = threadIdx.x; f < BQ_TILE; f += BQ_T) {
            float x = xb[(tb + f) * 3 + 0];
            float y = xb[(tb + f) * 3 + 1];
            float z = xb[(tb + f) * 3 + 2];
            sp[f] = make_float4(x, y, z, sq3_rn(x, y, z));
        }
        __syncthreads();

        for (int j = 0; j < BQ_TILE; j++) {
            float4 p = sp[j];
            float dot = __fadd_rn(__fadd_rn(__fmul_rn(cx, p.x), __fmul_rn(cy, p.y)), __fmul_rn(cz, p.z));
            float d2  = __fsub_rn(__fadd_rn(c2, p.w), __fmul_rn(2.0f, dot));
            d2 = fmaxf(d2, 0.0f);
            unsigned bits = (d2 <= Tf) ? __float_as_uint(d2) : 0x7f800000u;
            unsigned long long key = ((unsigned long long)bits << 32) | (unsigned)(tb + j);
            if (key < worst) {
                unsigned long long cur = key;
                #pragma unroll
                for (int k = 0; k < KK; k++) {
                    unsigned long long lo = (cur < list[k]) ? cur : list[k];
                    unsigned long long hi = (cur < list[k]) ? list[k] : cur;
                    list[k] = lo;
                    cur = hi;
                }
                worst = list[KK - 1];
            }
        }
    }

    int* o = g_knn + (size_t)(b * MM + m) * KK;
    #pragma unroll
    for (int k = 0; k < KK; k++) o[k] = (int)(list[k] & 0xffffffffULL);
}

// ---------------- GEMM core (unchanged R9 pair-A) ----------------
#define XS_LD  130
#define XS_BYTES  (68 * XS_LD * 4)
#define WSD_BYTES (68 * 64 * 8)
#define GEMM_SMEM (XS_BYTES + WSD_BYTES)

struct ABuf { unsigned long long a[4]; unsigned long long b[8]; };

__device__ __forceinline__ void ld_ab(const float* xp, const unsigned long long* wp,
                                      int k, ABuf& r) {
    #pragma unroll
    for (int q = 0; q < 4; q++)
        r.a[q] = *(const unsigned long long*)(xp + k * XS_LD + 32 * q);
    ulonglong2 b01 = *(const ulonglong2*)(wp + (size_t)k * 64 + 0);
    ulonglong2 b23 = *(const ulonglong2*)(wp + (size_t)k * 64 + 2);
    ulonglong2 b45 = *(const ulonglong2*)(wp + (size_t)k * 64 + 4);
    ulonglong2 b67 = *(const ulonglong2*)(wp + (size_t)k * 64 + 6);
    r.b[0] = b01.x; r.b[1] = b01.y; r.b[2] = b23.x; r.b[3] = b23.y;
    r.b[4] = b45.x; r.b[5] = b45.y; r.b[6] = b67.x; r.b[7] = b67.y;
}
__device__ __forceinline__ void fma_ab(unsigned long long acc[4][8], const ABuf& r) {
    #pragma unroll
    for (int q = 0; q < 4; q++)
        #pragma unroll
        for (int j = 0; j < 8; j++)
            asm("fma.rn.f32x2 %0, %1, %2, %0;" : "+l"(acc[q][j]) : "l"(r.a[q]), "l"(r.b[j]));
}
template <int KD>
__device__ __forceinline__ void gemm_mainloop(const float* Xs, const unsigned long long* Wsd,
                                              int t, unsigned long long acc[4][8]) {
    int rg = t & 15, cg = t >> 4;
    #pragma unroll
    for (int q = 0; q < 4; q++)
        #pragma unroll
        for (int j = 0; j < 8; j++) acc[q][j] = 0ULL;
    const unsigned long long* wp = Wsd + cg * 8;
    const float* xp = Xs + 2 * rg;
    ABuf A, B;
    constexpr int MAIN = (KD - 2) & ~1;
    ld_ab(xp, wp, 0, A);
    #pragma unroll 4
    for (int k = 0; k < MAIN; k += 2) {
        ld_ab(xp, wp, k + 1, B);
        fma_ab(acc, A);
        ld_ab(xp, wp, k + 2, A);
        fma_ab(acc, B);
    }
    ld_ab(xp, wp, MAIN + 1, B);
    fma_ab(acc, A);
    if (KD - MAIN == 3) {
        ld_ab(xp, wp, MAIN + 2, A);
        fma_ab(acc, B);
        fma_ab(acc, A);
    } else {
        fma_ab(acc, B);
    }
}

__device__ __forceinline__ void gemm_epi_store(
    unsigned long long acc[4][8], float* Xs,
    const float* bias, float* Y, int ldy,
    size_t row0, int col0, int t,
    float* stats, int sqoff)
{
    int rg = t & 15, cg = t >> 4;
    float bsum[8], bsq[8], bval[8];
    #pragma unroll
    for (int j = 0; j < 8; j++) { bsum[j] = 0.f; bsq[j] = 0.f; bval[j] = bias[col0 + cg * 8 + j]; }
    #pragma unroll
    for (int q = 0; q < 4; q++) {
        size_t r0 = row0 + 2 * rg + 32 * q;
        float y0[8], y1[8];
        #pragma unroll
        for (int j = 0; j < 8; j++) {
            float lo, hi;
            unpk2(acc[q][j], lo, hi);
            y0[j] = lo + bval[j];
            y1[j] = hi + bval[j];
            bsum[j] += y0[j] + y1[j];
            bsq[j]  = fmaf(y0[j], y0[j], fmaf(y1[j], y1[j], bsq[j]));
        }
        float* ya = Y + r0 * (size_t)ldy + col0 + cg * 8;
        float* yb = ya + ldy;
        *(float4*)(ya)     = make_float4(y0[0], y0[1], y0[2], y0[3]);
        *(float4*)(ya + 4) = make_float4(y0[4], y0[5], y0[6], y0[7]);
        *(float4*)(yb)     = make_float4(y1[0], y1[1], y1[2], y1[3]);
        *(float4*)(yb + 4) = make_float4(y1[4], y1[5], y1[6], y1[7]);
    }
    __syncthreads();
    float* csum = Xs;
    float* csq  = Xs + 64;
    if (t < 64) { csum[t] = 0.f; csq[t] = 0.f; }
    __syncthreads();
    #pragma unroll
    for (int j = 0; j < 8; j++) {
        atomicAdd(&csum[cg * 8 + j], bsum[j]);
        atomicAdd(&csq[cg * 8 + j], bsq[j]);
    }
    __syncthreads();
    if (t < 64) {
        atomicAdd(&stats[col0 + t], csum[t]);
        atomicAdd(&stats[sqoff + col0 + t], csq[t]);
    }
}

__device__ __forceinline__ void gemm_epi_max(
    unsigned long long acc[4][8], float* scr,
    const float* bias, size_t row0, int col0, int t,
    float* stats, int sqoff)
{
    int rg = t & 15, cg = t >> 4;
    int bm0 = (int)(row0 >> 5);
    float* sMax = scr;
    float* csum = scr + 4352;
    float* csq  = scr + 4416;

    float bsum[8], bsq[8], bval[8];
    #pragma unroll
    for (int j = 0; j < 8; j++) { bsum[j] = 0.f; bsq[j] = 0.f; bval[j] = bias[col0 + cg * 8 + j]; }
    #pragma unroll
    for (int q = 0; q < 4; q++) {
        #pragma unroll
        for (int j = 0; j < 8; j++) {
            float lo, hi;
            unpk2(acc[q][j], lo, hi);
            float y0 = lo + bval[j];
            float y1 = hi + bval[j];
            bsum[j] += y0 + y1;
            bsq[j]  = fmaf(y0, y0, fmaf(y1, y1, bsq[j]));
            sMax[(q * 64 + cg * 8 + j) * 17 + rg] = fmaxf(y0, y1);
        }
    }
    if (t < 64) { csum[t] = 0.f; csq[t] = 0.f; }
    __syncthreads();
    #pragma unroll
    for (int j = 0; j < 8; j++) {
        atomicAdd(&csum[cg * 8 + j], bsum[j]);
        atomicAdd(&csq[cg * 8 + j], bsq[j]);
    }
    __syncthreads();
    if (t < 64) {
        atomicAdd(&stats[col0 + t], csum[t]);
        atomicAdd(&stats[sqoff + col0 + t], csq[t]);
    }
    #pragma unroll
    for (int e = t; e < 256; e += 128) {
        int q = e >> 6, col = e & 63;
        const float* p = &sMax[(q * 64 + col) * 17];
        float mx = p[0];
        #pragma unroll
        for (int r = 1; r < 16; r++) mx = fmaxf(mx, p[r]);
        g_Ymax[(size_t)(bm0 + q) * 128 + col0 + col] = mx;
    }
}

__global__ void __launch_bounds__(128, 3) k_gemm0(const float* __restrict__ xyz,
                                                  const float* __restrict__ newxyz,
                                                  const float* __restrict__ W,
                                                  const float* __restrict__ bias,
                                                  float* __restrict__ Y) {
    extern __shared__ float sm[];
    float* Xs = sm;
    unsigned long long* Wsd = (unsigned long long*)(sm + 68 * XS_LD);
    int t = threadIdx.x, w = t >> 5, lane = t & 31;
    size_t row0 = (size_t)blockIdx.x * 128;
    int bm0 = (int)(row0 >> 5);
    int b   = bm0 >> 11;

    __shared__ int   s_idx[128];
    __shared__ float s_ctr[4][3];
    s_idx[t] = g_knn[row0 + t];
    if (t < 12) s_ctr[t / 3][t % 3] = newxyz[(size_t)bm0 * 3 + t];
    __syncthreads();

    const float* fb = g_featT + (size_t)b * NN * CIN;
    const float* xb = xyz + (size_t)b * NN * 3;

    float ctr = (lane < 3) ? s_ctr[w][lane] : 0.0f;
    #pragma unroll 4
    for (int rr = 0; rr < 32; rr++) {
        int r = w * 32 + rr;
        int n = s_idx[r];
        float2 v = *(const float2*)(fb + (size_t)n * CIN + lane * 2);
        Xs[(2 * lane) * XS_LD + r]     = v.x;
        Xs[(2 * lane + 1) * XS_LD + r] = v.y;
        if (lane < 3)
            Xs[(64 + lane) * XS_LD + r] = __fsub_rn(xb[n * 3 + lane], ctr);
    }
    {
        int tot = 64 * KD0;
        for (int e = t; e < tot; e += 128) {
            int o = e / KD0, k = e - o * KD0;
            int kk = (k < 64) ? (k + 3) : (k - 64);
            float wv = W[o * KD0 + kk];
            Wsd[k * 64 + o] = pk2(wv, wv);
        }
    }
    __syncthreads();
    unsigned long long acc[4][8];
    gemm_mainloop<KD0>(Xs, Wsd, t, acc);
    gemm_epi_store(acc, Xs, bias, Y, 64, row0, 0, t, g_stats0, 64);
}

__global__ void __launch_bounds__(128, 3) k_gemmx(const float* __restrict__ X,
                                                  const float* __restrict__ W,
                                                  const float* __restrict__ bias,
                                                  const float* __restrict__ gprm,
                                                  const float* __restrict__ btprm,
                                                  float* __restrict__ Y, int ldy) {
    extern __shared__ float sm[];
    float* Xs = sm;
    unsigned long long* Wsd = (unsigned long long*)(sm + 68 * XS_LD);
    int t = threadIdx.x;
    size_t row0 = (size_t)blockIdx.x * 128;
    int col0 = 0;
    {
        const float* xr = X + row0 * 64;
        int c = (t * 4) & 63;
        float sc[4], sh[4];
        #pragma unroll
        for (int q = 0; q < 4; q++) bn_ss(g_stats0, 64, gprm, btprm, c + q, sc[q], sh[q]);
        #pragma unroll
        for (int it = 0; it < 16; it++) {
            int idx = it * 512 + t * 4;
            int r = idx >> 6;
            float4 v = *(const float4*)(xr + idx);
            v.x = fmaxf(fmaf(v.x, sc[0], sh[0]), 0.0f);
            v.y = fmaxf(fmaf(v.y, sc[1], sh[1]), 0.0f);
            v.z = fmaxf(fmaf(v.z, sc[2], sh[2]), 0.0f);
            v.w = fmaxf(fmaf(v.w, sc[3], sh[3]), 0.0f);
            Xs[(c + 0) * XS_LD + r] = v.x;
            Xs[(c + 1) * XS_LD + r] = v.y;
            Xs[(c + 2) * XS_LD + r] = v.z;
            Xs[(c + 3) * XS_LD + r] = v.w;
        }
    }
    {
        const float* wb = W;
        #pragma unroll 4
        for (int e = t; e < 64 * 64; e += 128) {
            int o = e >> 6, k = e & 63;
            float wv = wb[o * 64 + k];
            Wsd[k * 64 + o] = pk2(wv, wv);
        }
    }
    __syncthreads();
    unsigned long long acc[4][8];
    gemm_mainloop<64>(Xs, Wsd, t, acc);
    gemm_epi_store(acc, Xs, bias, Y, ldy, row0, col0, t, g_stats1, 64);
}

__global__ void __launch_bounds__(128, 3) k_gemmf(const float* __restrict__ X,
                                                  const float* __restrict__ W,
                                                  const float* __restrict__ bias,
                                                  const float* __restrict__ gprm,
                                                  const float* __restrict__ btprm) {
    extern __shared__ float sm[];
    float* Xs = sm;
    unsigned long long* Wsd = (unsigned long long*)(sm + 68 * XS_LD);
    int t = threadIdx.x;
    size_t row0 = (size_t)blockIdx.x * 128;
    {
        const float* xr = X + row0 * 64;
        int c = (t * 4) & 63;
        float sc[4], sh[4];
        #pragma unroll
        for (int q = 0; q < 4; q++) bn_ss(g_stats1, 64, gprm, btprm, c + q, sc[q], sh[q]);
        #pragma unroll
        for (int it = 0; it < 16; it++) {
            int idx = it * 512 + t * 4;
            int r = idx >> 6;
            float4 v = *(const float4*)(xr + idx);
            v.x = fmaxf(fmaf(v.x, sc[0], sh[0]), 0.0f);
            v.y = fmaxf(fmaf(v.y, sc[1], sh[1]), 0.0f);
            v.z = fmaxf(fmaf(v.z, sc[2], sh[2]), 0.0f);
            v.w = fmaxf(fmaf(v.w, sc[3], sh[3]), 0.0f);
            Xs[(c + 0) * XS_LD + r] = v.x;
            Xs[(c + 1) * XS_LD + r] = v.y;
            Xs[(c + 2) * XS_LD + r] = v.z;
            Xs[(c + 3) * XS_LD + r] = v.w;
        }
    }
    #pragma unroll
    for (int ct = 0; ct < 2; ct++) {
        int col0 = ct * 64;
        {
            const float* wb = W + (size_t)col0 * 64;
            #pragma unroll 4
            for (int e = t; e < 64 * 64; e += 128) {
                int o = e >> 6, k = e & 63;
                float wv = wb[o * 64 + k];
                Wsd[k * 64 + o] = pk2(wv, wv);
            }
        }
        __syncthreads();
        unsigned long long acc[4][8];
        gemm_mainloop<64>(Xs, Wsd, t, acc);
        __syncthreads();
        gemm_epi_max(acc, (float*)Wsd, bias, row0, col0, t, g_stats2, 128);
        __syncthreads();
    }
}

__global__ void __launch_bounds__(128) k_final2(const float* __restrict__ gprm,
                                                const float* __restrict__ btprm,
                                                float* __restrict__ out) {
    __shared__ float tile[32][129];
    int bm0 = blockIdx.x * 32;
    int c  = threadIdx.x;
    float sc, sh;
    bn_ss(g_stats2, 128, gprm, btprm, c, sc, sh);
    #pragma unroll 4
    for (int mm = 0; mm < 32; mm++) {
        float y = g_Ymax[(size_t)(bm0 + mm) * 128 + c];
        tile[mm][c] = fmaxf(fmaf(y, sc, sh), 0.0f);
    }
    __syncthreads();
    int b  = bm0 >> 11;
    int m0 = bm0 & 2047;
    int w = c >> 5, lane = c & 31;
    #pragma unroll 4
    for (int rr = 0; rr < 32; rr++) {
        int cc = w * 32 + rr;
        out[(size_t)BB * MM * 3 + ((size_t)b * 128 + cc) * MM + m0 + lane] = tile[lane][cc];
    }
}

extern "C" void kernel_launch(void* const* d_in, const int* in_sizes, int n_in,
                              void* d_out, int out_size) {
    const float* xyz  = (const float*)d_in[0];
    const float* feat = (const float*)d_in[1];
    const float* w0 = (const float*)d_in[2];
    const float* b0 = (const float*)d_in[3];
    const float* g0 = (const float*)d_in[4];
    const float* t0 = (const float*)d_in[5];
    const float* w1 = (const float*)d_in[6];
    const float* b1 = (const float*)d_in[7];
    const float* g1 = (const float*)d_in[8];
    const float* t1 = (const float*)d_in[9];
    const float* w2 = (const float*)d_in[10];
    const float* b2 = (const float*)d_in[11];
    const float* g2 = (const float*)d_in[12];
    const float* t2 = (const float*)d_in[13];
    float* out = (float*)d_out;

    void *pY0, *pY1;
    cudaGetSymbolAddress(&pY0, g_Y0);
    cudaGetSymbolAddress(&pY1, g_Y1);
    float* Y0 = (float*)pY0;
    float* Y1 = (float*)pY1;

    cudaFuncSetAttribute(k_gemm0, cudaFuncAttributeMaxDynamicSharedMemorySize, GEMM_SMEM);
    cudaFuncSetAttribute(k_gemmx, cudaFuncAttributeMaxDynamicSharedMemorySize, GEMM_SMEM);
    cudaFuncSetAttribute(k_gemmf, cudaFuncAttributeMaxDynamicSharedMemorySize, GEMM_SMEM);

    k_fps_tr<<<32 + 2048, FPS_T>>>(xyz, feat, out);
    k_ballquery<<<BB * (MM / BQ_T), BQ_T>>>(xyz, out);
    k_gemm0<<<RTOT / 128, 128, GEMM_SMEM>>>(xyz, out, w0, b0, Y0);
    k_gemmx<<<RTOT / 128, 128, GEMM_SMEM>>>(Y0, w1, b1, g0, t0, Y1, 64);
    k_gemmf<<<RTOT / 128, 128, GEMM_SMEM>>>(Y1, w2, b2, g1, t1);
    k_final2<<<BB * MM / 32, 128>>>(g2, t2, out);
}